// round 10
// baseline (speedup 1.0000x reference)
#include <cuda_runtime.h>
#include <cstdint>

#define NROWS 8192
#define DIM   128
#define BM    128
#define BN    128
#define NTILES (NROWS / BN)                  // 64
#define NUNITS (NTILES * (NTILES + 1) / 2)   // 2080 triangle tile-pairs
#define GRID_MAIN 148
#define NTHREADS 512
#define RSTRIDE   130                        // floats/row: u64-stride 65 (odd) -> LDS.64 conflict-free
#define TILE_F (BM * RSTRIDE)                // 16640 floats per tile
#define MARGIN_F 0.3f

typedef unsigned long long u64;

// Scratch (device globals; no allocations allowed)
__device__ unsigned int g_ap2[NROWS];   // max same-label d^2 (float bits)
__device__ unsigned int g_an2[NROWS];   // min diff-label d^2 (float bits)
__device__ float        g_sq[NROWS];    // ||x_i||^2
__device__ int          g_lab[NROWS];   // normalized labels (int32)
__device__ unsigned int g_done;         // last-CTA election (reset each launch)

// ---------------------------------------------------------------------------
// Helpers
// ---------------------------------------------------------------------------
__device__ __forceinline__ unsigned smem_u32(const void* p) {
    unsigned r;
    asm("{ .reg .u64 t; cvta.to.shared.u64 t, %1; cvt.u32.u64 %0, t; }"
        : "=r"(r) : "l"(p));
    return r;
}
__device__ __forceinline__ void cp8(unsigned dst, const void* src) {
    asm volatile("cp.async.ca.shared.global [%0], [%1], 8;" :: "r"(dst), "l"(src));
}
__device__ __forceinline__ void cp4(unsigned dst, const void* src) {
    asm volatile("cp.async.ca.shared.global [%0], [%1], 4;" :: "r"(dst), "l"(src));
}
__device__ __forceinline__ void cp_commit() { asm volatile("cp.async.commit_group;"); }
__device__ __forceinline__ void cp_wait0()  { asm volatile("cp.async.wait_group 0;" ::: "memory"); }
__device__ __forceinline__ void cp_wait1()  { asm volatile("cp.async.wait_group 1;" ::: "memory"); }
__device__ __forceinline__ void cp_wait2()  { asm volatile("cp.async.wait_group 2;" ::: "memory"); }

// ---------------------------------------------------------------------------
// Fused prep: init mining buffers + row norms + label normalization.
// ---------------------------------------------------------------------------
__global__ void prep_kernel(const float* __restrict__ x, const int* __restrict__ t32) {
    int gid = blockIdx.x * 256 + threadIdx.x;
    if (gid < NROWS) { g_ap2[gid] = 0u; g_an2[gid] = 0x7f800000u; }

    int gwarp = gid >> 5;          // exactly 8192 warps
    int lane  = gid & 31;
    float4 v = reinterpret_cast<const float4*>(x + (size_t)gwarp * DIM)[lane];
    float s = v.x * v.x + v.y * v.y + v.z * v.z + v.w * v.w;
#pragma unroll
    for (int o = 16; o; o >>= 1) s += __shfl_xor_sync(0xffffffffu, s, o);
    if (lane == 0) g_sq[gwarp] = s;

    if (blockIdx.x == 0) {
        // targets may be int64 (odd int32 words all zero) or int32
        __shared__ int s_all64;
        if (threadIdx.x == 0) s_all64 = 1;
        __syncthreads();
        int local = 1;
        for (int i = threadIdx.x; i < 4096; i += 256)
            if (t32[2 * i + 1] != 0) local = 0;
        if (!local) atomicAnd(&s_all64, 0);
        __syncthreads();
        const bool is64 = (s_all64 != 0);
        for (int i = threadIdx.x; i < NROWS; i += 256)
            g_lab[i] = is64 ? t32[2 * i] : t32[i];
    }
}

// ---------------------------------------------------------------------------
// Tile loader: global row-major [rows][128] -> smem rows of stride 130 floats
// (8B-aligned rows: 520 mod 8 == 0). 512 threads, 8 iterations.
// ---------------------------------------------------------------------------
__device__ __forceinline__ void load_tile_async(unsigned dst_u32,
                                                const float* __restrict__ x,
                                                int rowbase, int tid) {
#pragma unroll
    for (int i = 0; i < 8; i++) {
        int idx = tid + i * NTHREADS;  // 0..4095
        int row = idx >> 5;            // 0..127
        int q   = idx & 31;            // float4 chunk
        const float* src = x + (size_t)(rowbase + row) * DIM + q * 4;
        unsigned d = dst_u32 + (unsigned)(row * RSTRIDE + q * 4) * 4u;
        cp8(d, src);
        cp8(d + 8, src + 2);
    }
}

// ---------------------------------------------------------------------------
// Main persistent kernel: triangle tile-pairs (ti <= tj).
// 512 threads (4 warps/SMSP for latency hiding), 8x4 micro-tile, packed
// fma.rn.f32x2, double-buffered B, aliased-diagonal async A refill,
// inline finalize.
// Thread grid: tx = lane (0..31) -> cols tx+32c (c<4); ty = warp (0..15)
// -> rows ty+16r (r<8). A-loads warp-broadcast; B-loads conflict-free
// (u64 row stride 65, (lane*65) mod 16 bijective per phase).
// ---------------------------------------------------------------------------
__global__ void __launch_bounds__(NTHREADS, 1)
triplet_main_kernel(const float* __restrict__ x, float* __restrict__ out, int out_size) {
    extern __shared__ float smem[];
    float* Bs0   = smem;                       // [128][130]
    float* Bs1   = smem + TILE_F;
    float* As    = smem + 2 * TILE_F;          // [128][130]
    float* sqis  = smem + 3 * TILE_F;          // [128]
    int*   labis = (int*)(sqis + BM);          // [128]
    float* sqjs  = (float*)(labis + BM);       // [2][128]
    int*   labjs = (int*)(sqjs + 2 * BN);      // [2][128]
    float* colAp = (float*)(labjs + 2 * BN);   // [16][128]
    float* colAn = colAp + 16 * BN;            // [16][128]

    const int tid = threadIdx.x;
    const int tx = tid & 31;        // lane -> column group
    const int ty = tid >> 5;        // warp -> row group (0..15)

    const unsigned Bs0_u   = smem_u32(Bs0);
    const unsigned Bs1_u   = smem_u32(Bs1);
    const unsigned As_u    = smem_u32(As);
    const unsigned sqis_u  = smem_u32(sqis);
    const unsigned labis_u = smem_u32(labis);
    const unsigned sqjs_u  = smem_u32(sqjs);
    const unsigned labjs_u = smem_u32(labjs);

    // Static contiguous unit range (row-major triangle order -> A-tile reuse).
    int u0 = (int)((long long)blockIdx.x * NUNITS / gridDim.x);
    int u1 = (int)((long long)(blockIdx.x + 1) * NUNITS / gridDim.x);

    int ti = 0, rem = u0;
    while (rem >= NTILES - ti) { rem -= NTILES - ti; ti++; }
    int tj = ti + rem;

    // Prologue group: A tile + B(u0) tile + meta
    load_tile_async(As_u, x, ti * BM, tid);
    load_tile_async(Bs0_u, x, tj * BN, tid);
    if (tid < BM) {
        cp4(sqis_u + tid * 4,  g_sq  + ti * BM + tid);
        cp4(labis_u + tid * 4, g_lab + ti * BM + tid);
        cp4(sqjs_u + tid * 4,  g_sq  + tj * BN + tid);
        cp4(labjs_u + tid * 4, g_lab + tj * BN + tid);
    }
    cp_commit();

    bool alias = false;  // current unit reads A from its B buffer (fresh diagonal)

    for (int u = u0; u < u1; ++u) {
        const int buf = (u - u0) & 1;
        int nti = ti, ntj = tj + 1;
        if (ntj == NTILES) { nti = ti + 1; ntj = nti; }
        const bool has_next = (u + 1 < u1);

        int ncommit = 0;
        if (has_next) {
            load_tile_async(buf ? Bs0_u : Bs1_u, x, ntj * BN, tid);
            if (tid < BN) {
                cp4(sqjs_u + ((buf ^ 1) * BN + tid) * 4,  g_sq  + ntj * BN + tid);
                cp4(labjs_u + ((buf ^ 1) * BN + tid) * 4, g_lab + ntj * BN + tid);
            }
            cp_commit(); ncommit++;
        }
        // Aliased diagonal: As is idle this unit -> refill it asynchronously,
        // but only if a same-row (non-diagonal) unit will actually use it.
        if (alias && has_next && nti == ti) {
            load_tile_async(As_u, x, ti * BM, tid);
            if (tid < BM) {
                cp4(sqis_u + tid * 4,  g_sq  + ti * BM + tid);
                cp4(labis_u + tid * 4, g_lab + ti * BM + tid);
            }
            cp_commit(); ncommit++;
        }
        if (ncommit == 0)      cp_wait0();
        else if (ncommit == 1) cp_wait1();
        else                   cp_wait2();
        __syncthreads();

        const float* bbuf  = buf ? Bs1 : Bs0;
        const float* abuf  = alias ? bbuf : As;
        const float* sqip  = alias ? (sqjs + buf * BN)  : sqis;
        const int*   labip = alias ? (labjs + buf * BN) : labis;

        // ---- GEMM: acc[r][c] holds packed (even-k, odd-k) partial sums ----
        u64 acc[8][4];
#pragma unroll
        for (int r = 0; r < 8; r++)
#pragma unroll
            for (int c = 0; c < 4; c++) acc[r][c] = 0ull;

        const char* aB = (const char*)abuf + ty * (RSTRIDE * 4);   // rows ty+16r
        const char* bB = (const char*)bbuf + tx * (RSTRIDE * 4);   // cols tx+32c

#pragma unroll 4
        for (int k2 = 0; k2 < DIM / 2; ++k2) {
            u64 a[8], b[4];
#pragma unroll
            for (int r = 0; r < 8; r++)
                a[r] = *(const u64*)(aB + r * (16 * RSTRIDE * 4) + k2 * 8);
#pragma unroll
            for (int c = 0; c < 4; c++)
                b[c] = *(const u64*)(bB + c * (32 * RSTRIDE * 4) + k2 * 8);
#pragma unroll
            for (int r = 0; r < 8; r++)
#pragma unroll
                for (int c = 0; c < 4; c++)
                    asm("fma.rn.f32x2 %0, %1, %2, %0;"
                        : "+l"(acc[r][c]) : "l"(a[r]), "l"(b[c]));
        }

        // ---- Epilogue: d^2 mining, row (i) and column (j) sides ----
        float sjv[4]; int ljv[4];
#pragma unroll
        for (int c = 0; c < 4; c++) {
            sjv[c] = sqjs[buf * BN + tx + 32 * c];
            ljv[c] = labjs[buf * BN + tx + 32 * c];
        }
        float ap[8], an[8], apc[4], anc[4];
#pragma unroll
        for (int r = 0; r < 8; r++) { ap[r] = 0.0f; an[r] = __int_as_float(0x7f800000); }
#pragma unroll
        for (int c = 0; c < 4; c++) { apc[c] = 0.0f; anc[c] = __int_as_float(0x7f800000); }
#pragma unroll
        for (int r = 0; r < 8; r++) {
            float si = sqip[ty + 16 * r];
            int   li = labip[ty + 16 * r];
#pragma unroll
            for (int c = 0; c < 4; c++) {
                float2 p = *reinterpret_cast<float2*>(&acc[r][c]);
                float d2 = fmaf(-2.0f, p.x + p.y, si + sjv[c]);
                d2 = fmaxf(d2, 1e-12f);
                if (li == ljv[c]) { ap[r] = fmaxf(ap[r], d2); apc[c] = fmaxf(apc[c], d2); }
                else              { an[r] = fminf(an[r], d2); anc[c] = fminf(anc[c], d2); }
            }
        }

        // Row side: rows identical across the warp -> full 32-lane reduce,
        // lane 0 atomics (d2 > 0 -> uint order == float order).
#pragma unroll
        for (int o = 16; o; o >>= 1)
#pragma unroll
            for (int r = 0; r < 8; r++) {
                ap[r] = fmaxf(ap[r], __shfl_xor_sync(0xffffffffu, ap[r], o));
                an[r] = fminf(an[r], __shfl_xor_sync(0xffffffffu, an[r], o));
            }
        if (tx == 0) {
#pragma unroll
            for (int r = 0; r < 8; r++) {
                int row = ti * BM + ty + 16 * r;
                atomicMax(&g_ap2[row], __float_as_uint(ap[r]));
                atomicMin(&g_an2[row], __float_as_uint(an[r]));
            }
        }

        // Col side: stage per-warp partials (each warp covers all 128 cols),
        // combine across the 16 warps, then atomics.
#pragma unroll
        for (int c = 0; c < 4; c++) {
            colAp[ty * BN + tx + 32 * c] = apc[c];
            colAn[ty * BN + tx + 32 * c] = anc[c];
        }
        __syncthreads();
        if (tid < BN) {
            float ca = colAp[tid], cn = colAn[tid];
#pragma unroll
            for (int w = 1; w < 16; w++) {
                ca = fmaxf(ca, colAp[w * BN + tid]);
                cn = fminf(cn, colAn[w * BN + tid]);
            }
            atomicMax(&g_ap2[tj * BN + tid], __float_as_uint(ca));
            atomicMin(&g_an2[tj * BN + tid], __float_as_uint(cn));
        }
        __syncthreads();

        alias = has_next && (nti != ti);  // next unit is a fresh diagonal
        ti = nti; tj = ntj;
    }

    // ---- Inline finalize: last CTA computes loss + precision ----
    __threadfence();
    __syncthreads();
    __shared__ unsigned s_rank;
    if (tid == 0) s_rank = atomicAdd(&g_done, 1u);
    __syncthreads();
    if (s_rank == (unsigned)(gridDim.x - 1)) {
        float* scrL = Bs0;          // reuse B smem as reduction scratch
        float* scrP = Bs0 + NTHREADS;
        float loss = 0.0f, prec = 0.0f;
        for (int i = tid; i < NROWS; i += NTHREADS) {
            float dap = sqrtf(__uint_as_float(__ldcg(&g_ap2[i])));
            float dan = sqrtf(__uint_as_float(__ldcg(&g_an2[i])));
            loss += fmaxf(0.0f, MARGIN_F - (dan - dap));
            prec += (dan > dap) ? 1.0f : 0.0f;
        }
        scrL[tid] = loss;
        scrP[tid] = prec;
        __syncthreads();
#pragma unroll
        for (int s = NTHREADS / 2; s > 0; s >>= 1) {
            if (tid < s) {
                scrL[tid] += scrL[tid + s];
                scrP[tid] += scrP[tid + s];
            }
            __syncthreads();
        }
        if (tid == 0) {
            out[0] = scrL[0] / (float)NROWS;
            if (out_size > 1) out[1] = scrP[0] / (float)NROWS;
            g_done = 0;  // reset for next graph replay
        }
    }
}

// ---------------------------------------------------------------------------
extern "C" void kernel_launch(void* const* d_in, const int* in_sizes, int n_in,
                              void* d_out, int out_size) {
    const float* x   = (const float*)d_in[0];
    const int*   t32 = (const int*)d_in[1];
    (void)in_sizes; (void)n_in;

    const int smem_bytes =
        (3 * TILE_F + BM + BM + 2 * BN + 2 * BN + 16 * BN + 16 * BN) * 4;
    cudaFuncSetAttribute(triplet_main_kernel,
                         cudaFuncAttributeMaxDynamicSharedMemorySize, smem_bytes);

    prep_kernel<<<NROWS * 32 / 256, 256>>>(x, t32);
    triplet_main_kernel<<<GRID_MAIN, NTHREADS, smem_bytes>>>(x, (float*)d_out, out_size);
}

// round 12
// speedup vs baseline: 2.0100x; 2.0100x over previous
#include <cuda_runtime.h>
#include <cuda_bf16.h>
#include <cstdint>

#define NROWS 8192
#define DIM   128
#define NTILES 64
#define NUNITS (NTILES * (NTILES + 1) / 2)   // 2080
#define GRID_MAIN 148
#define NTHREADS 256
#define MARGIN_F 0.3f

#define ROW_B   528                           // smem bytes/row: 33*16 (odd) -> ldmatrix conflict-free
#define TILE_BYTES (128 * ROW_B)              // 67584
#define SM_A     0
#define SM_B0    TILE_BYTES
#define SM_B1    (2 * TILE_BYTES)
#define SM_METAI (3 * TILE_BYTES)             // 128 float2
#define SM_METAJ (SM_METAI + 1024)            // 2 x 128 float2
#define SM_TOTAL (SM_METAJ + 2048)

__device__ unsigned int  g_ap2[NROWS];
__device__ unsigned int  g_an2[NROWS];
__device__ float2        g_meta[NROWS];              // (||x||^2 fp32, label-as-float)
__device__ unsigned int  g_done;
__device__ __align__(512) __nv_bfloat16 g_split[NROWS * 256]; // per row: 128 hi | 128 lo

// ---------------------------------------------------------------------------
__device__ __forceinline__ unsigned smem_u32(const void* p) {
    unsigned r;
    asm("{ .reg .u64 t; cvta.to.shared.u64 t, %1; cvt.u32.u64 %0, t; }" : "=r"(r) : "l"(p));
    return r;
}
__device__ __forceinline__ void cp16(unsigned dst, const void* src) {
    asm volatile("cp.async.cg.shared.global [%0], [%1], 16;" :: "r"(dst), "l"(src));
}
__device__ __forceinline__ void cp_commit() { asm volatile("cp.async.commit_group;"); }
__device__ __forceinline__ void cp_waitn(int n) {
    if (n == 0)      asm volatile("cp.async.wait_group 0;" ::: "memory");
    else if (n == 1) asm volatile("cp.async.wait_group 1;" ::: "memory");
    else             asm volatile("cp.async.wait_group 2;" ::: "memory");
}
__device__ __forceinline__ void ldmx4(uint32_t* r, unsigned addr) {
    asm volatile("ldmatrix.sync.aligned.m8n8.x4.shared.b16 {%0,%1,%2,%3}, [%4];"
                 : "=r"(r[0]), "=r"(r[1]), "=r"(r[2]), "=r"(r[3]) : "r"(addr));
}
__device__ __forceinline__ void mma16816(float* d, const uint32_t* a, uint32_t b0, uint32_t b1) {
    asm volatile("mma.sync.aligned.m16n8k16.row.col.f32.bf16.bf16.f32 "
                 "{%0,%1,%2,%3}, {%4,%5,%6,%7}, {%8,%9}, {%0,%1,%2,%3};"
                 : "+f"(d[0]), "+f"(d[1]), "+f"(d[2]), "+f"(d[3])
                 : "r"(a[0]), "r"(a[1]), "r"(a[2]), "r"(a[3]), "r"(b0), "r"(b1));
}

// ---------------------------------------------------------------------------
// Prep: init mining buffers, bf16 hi/lo split, fp32 norms, labels. 1 warp/row.
// ---------------------------------------------------------------------------
__global__ void prep_kernel(const float* __restrict__ x, const int* __restrict__ t32) {
    int tid = threadIdx.x;
    int gid = blockIdx.x * 256 + tid;
    if (gid < NROWS) { g_ap2[gid] = 0u; g_an2[gid] = 0x7f800000u; }

    __shared__ int s_all64;
    if (tid == 0) s_all64 = 1;
    __syncthreads();
    int local = 1;
    for (int i = tid; i < 4096; i += 256)
        if (t32[2 * i + 1] != 0) local = 0;
    if (!local) atomicAnd(&s_all64, 0);
    __syncthreads();
    const bool is64 = (s_all64 != 0);

    int row = gid >> 5, lane = gid & 31;
    float4 v = reinterpret_cast<const float4*>(x + (size_t)row * DIM)[lane];
    __nv_bfloat16 h0 = __float2bfloat16(v.x), h1 = __float2bfloat16(v.y);
    __nv_bfloat16 h2 = __float2bfloat16(v.z), h3 = __float2bfloat16(v.w);
    __nv_bfloat16 l0 = __float2bfloat16(v.x - __bfloat162float(h0));
    __nv_bfloat16 l1 = __float2bfloat16(v.y - __bfloat162float(h1));
    __nv_bfloat16 l2 = __float2bfloat16(v.z - __bfloat162float(h2));
    __nv_bfloat16 l3 = __float2bfloat16(v.w - __bfloat162float(h3));
    __nv_bfloat162* ph = reinterpret_cast<__nv_bfloat162*>(g_split + (size_t)row * 256 + lane * 4);
    __nv_bfloat162* pl = reinterpret_cast<__nv_bfloat162*>(g_split + (size_t)row * 256 + 128 + lane * 4);
    ph[0] = __halves2bfloat162(h0, h1); ph[1] = __halves2bfloat162(h2, h3);
    pl[0] = __halves2bfloat162(l0, l1); pl[1] = __halves2bfloat162(l2, l3);

    float s = v.x * v.x + v.y * v.y + v.z * v.z + v.w * v.w;
#pragma unroll
    for (int o = 16; o; o >>= 1) s += __shfl_xor_sync(0xffffffffu, s, o);
    if (lane == 0) {
        int lab = is64 ? t32[2 * row] : t32[row];
        g_meta[row] = make_float2(s, (float)lab);
    }
}

// ---------------------------------------------------------------------------
// Tile loader: 128 rows x 512B (hi|lo) -> smem rows stride 528B.
// ---------------------------------------------------------------------------
__device__ __forceinline__ void load_tile(unsigned dst_u32, int rowbase, int tid) {
#pragma unroll
    for (int i = 0; i < 16; i++) {
        int idx = tid + i * NTHREADS;        // 0..4095 16B pieces
        int row = idx >> 5;
        int q   = idx & 31;
        cp16(dst_u32 + (unsigned)(row * ROW_B + q * 16),
             g_split + (size_t)(rowbase + row) * 256 + q * 8);
    }
}
__device__ __forceinline__ void load_meta(unsigned dst_u32, int rowbase, int tid) {
    if (tid < 64) cp16(dst_u32 + tid * 16, g_meta + rowbase + tid * 2);
}

// ---------------------------------------------------------------------------
// Main persistent kernel: triangle tile-pairs on mma.sync bf16-split HMMA.
// 8 warps; warp tile 32x64 (wrow=(wid&3)*32, wcol=(wid>>2)*64).
// ---------------------------------------------------------------------------
__global__ void __launch_bounds__(NTHREADS, 1)
triplet_main_kernel(float* __restrict__ out, int out_size) {
    extern __shared__ char smem[];
    const int tid  = threadIdx.x;
    const int wid  = tid >> 5, lane = tid & 31;
    const int g    = lane >> 2, q = lane & 3;
    const int wrow = (wid & 3) * 32;
    const int wcol = (wid >> 2) * 64;

    const unsigned sb  = smem_u32(smem);
    const unsigned AsU = sb + SM_A, B0U = sb + SM_B0, B1U = sb + SM_B1;
    const float2* metaI = (const float2*)(smem + SM_METAI);
    const float2* metaJ = (const float2*)(smem + SM_METAJ);

    int u0 = (int)((long long)blockIdx.x * NUNITS / gridDim.x);
    int u1 = (int)((long long)(blockIdx.x + 1) * NUNITS / gridDim.x);
    int ti = 0, rem = u0;
    while (rem >= NTILES - ti) { rem -= NTILES - ti; ti++; }
    int tj = ti + rem;

    // Prologue: A tile + B(u0) tile + meta (one group)
    load_tile(AsU, ti * 128, tid);
    load_meta(sb + SM_METAI, ti * 128, tid);
    load_tile(B0U, tj * 128, tid);
    load_meta(sb + SM_METAJ, tj * 128, tid);
    cp_commit();

    bool alias = false;   // current unit reads A from its B buffer (fresh diagonal)

    for (int u = u0; u < u1; ++u) {
        const int b = (u - u0) & 1;
        int nti = ti, ntj = tj + 1;
        if (ntj == NTILES) { nti = ti + 1; ntj = nti; }
        const bool has_next = (u + 1 < u1);

        int nc = 0;
        if (has_next) {
            load_tile(b ? B0U : B1U, ntj * 128, tid);
            load_meta(sb + SM_METAJ + (b ^ 1) * 1024, ntj * 128, tid);
            cp_commit(); nc++;
        }
        if (alias && has_next && nti == ti) {   // refill stale A during diagonal unit
            load_tile(AsU, ti * 128, tid);
            load_meta(sb + SM_METAI, ti * 128, tid);
            cp_commit(); nc++;
        }
        cp_waitn(nc);
        __syncthreads();

        const unsigned bU = b ? B1U : B0U;
        const unsigned aU = alias ? bU : AsU;
        const float2* mI = alias ? (metaJ + b * 128) : metaI;
        const float2* mJ = metaJ + b * 128;

        // Lane base addresses for ldmatrix (x4 quad-matrix layout).
        const unsigned aA = aU + (unsigned)((wrow + (lane & 15)) * ROW_B + (lane >> 4) * 16);
        const unsigned bA = bU + (unsigned)((wcol + ((lane >> 4) * 8) + (lane & 7)) * ROW_B
                                            + ((lane >> 3) & 1) * 16);

        float acc[2][8][4];
#pragma unroll
        for (int mf = 0; mf < 2; mf++)
#pragma unroll
            for (int nf = 0; nf < 8; nf++)
#pragma unroll
                for (int e = 0; e < 4; e++) acc[mf][nf][e] = 0.0f;

#pragma unroll
        for (int ks = 0; ks < 8; ks++) {
            const unsigned ko = ks * 32;          // k16 step, bytes
            uint32_t ah[2][4], al[2][4], bh[4][4], bl[4][4];
#pragma unroll
            for (int mf = 0; mf < 2; mf++) {
                ldmx4(ah[mf], aA + mf * (16 * ROW_B) + ko);         // A hi
                ldmx4(al[mf], aA + mf * (16 * ROW_B) + 256 + ko);   // A lo (elem offset 128)
            }
#pragma unroll
            for (int nb = 0; nb < 4; nb++) {
                ldmx4(bh[nb], bA + nb * (16 * ROW_B) + ko);         // B hi
                ldmx4(bl[nb], bA + nb * (16 * ROW_B) + 256 + ko);   // B lo
            }
#pragma unroll
            for (int mf = 0; mf < 2; mf++)
#pragma unroll
                for (int nb = 0; nb < 4; nb++) {
                    mma16816(acc[mf][nb * 2],     ah[mf], bh[nb][0], bh[nb][1]);  // hh
                    mma16816(acc[mf][nb * 2 + 1], ah[mf], bh[nb][2], bh[nb][3]);
                    mma16816(acc[mf][nb * 2],     ah[mf], bl[nb][0], bl[nb][1]);  // hl
                    mma16816(acc[mf][nb * 2 + 1], ah[mf], bl[nb][2], bl[nb][3]);
                    mma16816(acc[mf][nb * 2],     al[mf], bh[nb][0], bh[nb][1]);  // lh
                    mma16816(acc[mf][nb * 2 + 1], al[mf], bh[nb][2], bh[nb][3]);
                }
        }

        // ---- Epilogue: mine d^2 from fragments (row + col sides) ----
        float si4[4], li4[4];
#pragma unroll
        for (int rr = 0; rr < 4; rr++) {
            float2 m = mI[wrow + (rr >> 1) * 16 + (rr & 1) * 8 + g];
            si4[rr] = m.x; li4[rr] = m.y;
        }
        float sjv[16], ljv[16];
#pragma unroll
        for (int cc = 0; cc < 16; cc++) {
            float2 m = mJ[wcol + (cc >> 1) * 8 + q * 2 + (cc & 1)];
            sjv[cc] = m.x; ljv[cc] = m.y;
        }
        float ap4[4], an4[4], apc[16], anc[16];
#pragma unroll
        for (int rr = 0; rr < 4; rr++) { ap4[rr] = 0.0f; an4[rr] = __int_as_float(0x7f800000); }
#pragma unroll
        for (int cc = 0; cc < 16; cc++) { apc[cc] = 0.0f; anc[cc] = __int_as_float(0x7f800000); }

#pragma unroll
        for (int mf = 0; mf < 2; mf++)
#pragma unroll
            for (int nf = 0; nf < 8; nf++)
#pragma unroll
                for (int e = 0; e < 4; e++) {
                    int rr = mf * 2 + (e >> 1);
                    int cc = nf * 2 + (e & 1);
                    float d2 = fmaf(-2.0f, acc[mf][nf][e], si4[rr] + sjv[cc]);
                    d2 = fmaxf(d2, 1e-12f);
                    if (li4[rr] == ljv[cc]) {
                        ap4[rr] = fmaxf(ap4[rr], d2); apc[cc] = fmaxf(apc[cc], d2);
                    } else {
                        an4[rr] = fminf(an4[rr], d2); anc[cc] = fminf(anc[cc], d2);
                    }
                }

        // Row side: reduce over the quad (lanes share row when g equal).
#pragma unroll
        for (int o = 1; o <= 2; o <<= 1)
#pragma unroll
            for (int rr = 0; rr < 4; rr++) {
                ap4[rr] = fmaxf(ap4[rr], __shfl_xor_sync(0xffffffffu, ap4[rr], o));
                an4[rr] = fminf(an4[rr], __shfl_xor_sync(0xffffffffu, an4[rr], o));
            }
        if (q == 0) {
#pragma unroll
            for (int rr = 0; rr < 4; rr++) {
                int row = ti * 128 + wrow + (rr >> 1) * 16 + (rr & 1) * 8 + g;
                atomicMax(&g_ap2[row], __float_as_uint(ap4[rr]));
                atomicMin(&g_an2[row], __float_as_uint(an4[rr]));
            }
        }
        // Col side: reduce over g (xor 4,8,16), lanes 0-3 write.
#pragma unroll
        for (int o = 4; o <= 16; o <<= 1)
#pragma unroll
            for (int cc = 0; cc < 16; cc++) {
                apc[cc] = fmaxf(apc[cc], __shfl_xor_sync(0xffffffffu, apc[cc], o));
                anc[cc] = fminf(anc[cc], __shfl_xor_sync(0xffffffffu, anc[cc], o));
            }
        if (lane < 4) {
#pragma unroll
            for (int cc = 0; cc < 16; cc++) {
                int col = tj * 128 + wcol + (cc >> 1) * 8 + q * 2 + (cc & 1);
                atomicMax(&g_ap2[col], __float_as_uint(apc[cc]));
                atomicMin(&g_an2[col], __float_as_uint(anc[cc]));
            }
        }
        __syncthreads();   // all reads of current buffers done before next prefetch

        alias = has_next && (nti != ti);
        ti = nti; tj = ntj;
    }

    // ---- Inline finalize: last CTA computes loss + precision ----
    __threadfence();
    __syncthreads();
    __shared__ unsigned s_rank;
    if (tid == 0) s_rank = atomicAdd(&g_done, 1u);
    __syncthreads();
    if (s_rank == (unsigned)(gridDim.x - 1)) {
        float* scrL = (float*)smem;
        float* scrP = scrL + NTHREADS;
        float loss = 0.0f, prec = 0.0f;
        for (int i = tid; i < NROWS; i += NTHREADS) {
            float dap = sqrtf(__uint_as_float(__ldcg(&g_ap2[i])));
            float dan = sqrtf(__uint_as_float(__ldcg(&g_an2[i])));
            loss += fmaxf(0.0f, MARGIN_F - (dan - dap));
            prec += (dan > dap) ? 1.0f : 0.0f;
        }
        scrL[tid] = loss; scrP[tid] = prec;
        __syncthreads();
#pragma unroll
        for (int s = NTHREADS / 2; s > 0; s >>= 1) {
            if (tid < s) { scrL[tid] += scrL[tid + s]; scrP[tid] += scrP[tid + s]; }
            __syncthreads();
        }
        if (tid == 0) {
            out[0] = scrL[0] / (float)NROWS;
            if (out_size > 1) out[1] = scrP[0] / (float)NROWS;
            g_done = 0;
        }
    }
}

// ---------------------------------------------------------------------------
extern "C" void kernel_launch(void* const* d_in, const int* in_sizes, int n_in,
                              void* d_out, int out_size) {
    const float* x   = (const float*)d_in[0];
    const int*   t32 = (const int*)d_in[1];
    (void)in_sizes; (void)n_in;

    cudaFuncSetAttribute(triplet_main_kernel,
                         cudaFuncAttributeMaxDynamicSharedMemorySize, SM_TOTAL);
    prep_kernel<<<NROWS * 32 / 256, 256>>>(x, t32);
    triplet_main_kernel<<<GRID_MAIN, NTHREADS, SM_TOTAL>>>((float*)d_out, out_size);
}

// round 13
// speedup vs baseline: 2.0212x; 1.0056x over previous
#include <cuda_runtime.h>
#include <cuda_bf16.h>
#include <cstdint>

#define NROWS 8192
#define DIM   128
#define NTILES 64
#define NUNITS (NTILES * (NTILES + 1) / 2)   // 2080
#define GRID_MAIN 148
#define NTHREADS 512
#define MARGIN_F 0.3f

#define ROW_B   528                           // smem bytes/row: 33*16 (odd) -> ldmatrix conflict-free
#define TILE_BYTES (128 * ROW_B)              // 67584
#define SM_A     0
#define SM_B0    TILE_BYTES
#define SM_B1    (2 * TILE_BYTES)
#define SM_METAI (3 * TILE_BYTES)             // 128 float2
#define SM_METAJ (SM_METAI + 1024)            // 2 x 128 float2
#define SM_TOTAL (SM_METAJ + 2048)

__device__ unsigned int  g_ap2[NROWS];
__device__ unsigned int  g_an2[NROWS];
__device__ float2        g_meta[NROWS];              // (||x||^2 fp32, label-as-float)
__device__ unsigned int  g_done;
__device__ __align__(512) __nv_bfloat16 g_split[NROWS * 256]; // per row: 128 hi | 128 lo

// ---------------------------------------------------------------------------
__device__ __forceinline__ unsigned smem_u32(const void* p) {
    unsigned r;
    asm("{ .reg .u64 t; cvta.to.shared.u64 t, %1; cvt.u32.u64 %0, t; }" : "=r"(r) : "l"(p));
    return r;
}
__device__ __forceinline__ void cp16(unsigned dst, const void* src) {
    asm volatile("cp.async.cg.shared.global [%0], [%1], 16;" :: "r"(dst), "l"(src));
}
__device__ __forceinline__ void cp_commit() { asm volatile("cp.async.commit_group;"); }
__device__ __forceinline__ void cp_waitn(int n) {
    if (n == 0)      asm volatile("cp.async.wait_group 0;" ::: "memory");
    else if (n == 1) asm volatile("cp.async.wait_group 1;" ::: "memory");
    else             asm volatile("cp.async.wait_group 2;" ::: "memory");
}
__device__ __forceinline__ void ldmx4(uint32_t* r, unsigned addr) {
    asm volatile("ldmatrix.sync.aligned.m8n8.x4.shared.b16 {%0,%1,%2,%3}, [%4];"
                 : "=r"(r[0]), "=r"(r[1]), "=r"(r[2]), "=r"(r[3]) : "r"(addr));
}
__device__ __forceinline__ void mma16816(float* d, const uint32_t* a, uint32_t b0, uint32_t b1) {
    asm volatile("mma.sync.aligned.m16n8k16.row.col.f32.bf16.bf16.f32 "
                 "{%0,%1,%2,%3}, {%4,%5,%6,%7}, {%8,%9}, {%0,%1,%2,%3};"
                 : "+f"(d[0]), "+f"(d[1]), "+f"(d[2]), "+f"(d[3])
                 : "r"(a[0]), "r"(a[1]), "r"(a[2]), "r"(a[3]), "r"(b0), "r"(b1));
}

// ---------------------------------------------------------------------------
// Prep: init mining buffers, bf16 hi/lo split, fp32 norms, labels. 1 warp/row.
// ---------------------------------------------------------------------------
__global__ void prep_kernel(const float* __restrict__ x, const int* __restrict__ t32) {
    int tid = threadIdx.x;
    int gid = blockIdx.x * 256 + tid;
    if (gid < NROWS) { g_ap2[gid] = 0u; g_an2[gid] = 0x7f800000u; }

    __shared__ int s_all64;
    if (tid == 0) s_all64 = 1;
    __syncthreads();
    int local = 1;
    for (int i = tid; i < 4096; i += 256)
        if (t32[2 * i + 1] != 0) local = 0;
    if (!local) atomicAnd(&s_all64, 0);
    __syncthreads();
    const bool is64 = (s_all64 != 0);

    int row = gid >> 5, lane = gid & 31;
    float4 v = reinterpret_cast<const float4*>(x + (size_t)row * DIM)[lane];
    __nv_bfloat16 h0 = __float2bfloat16(v.x), h1 = __float2bfloat16(v.y);
    __nv_bfloat16 h2 = __float2bfloat16(v.z), h3 = __float2bfloat16(v.w);
    __nv_bfloat16 l0 = __float2bfloat16(v.x - __bfloat162float(h0));
    __nv_bfloat16 l1 = __float2bfloat16(v.y - __bfloat162float(h1));
    __nv_bfloat16 l2 = __float2bfloat16(v.z - __bfloat162float(h2));
    __nv_bfloat16 l3 = __float2bfloat16(v.w - __bfloat162float(h3));
    __nv_bfloat162* ph = reinterpret_cast<__nv_bfloat162*>(g_split + (size_t)row * 256 + lane * 4);
    __nv_bfloat162* pl = reinterpret_cast<__nv_bfloat162*>(g_split + (size_t)row * 256 + 128 + lane * 4);
    ph[0] = __halves2bfloat162(h0, h1); ph[1] = __halves2bfloat162(h2, h3);
    pl[0] = __halves2bfloat162(l0, l1); pl[1] = __halves2bfloat162(l2, l3);

    float s = v.x * v.x + v.y * v.y + v.z * v.z + v.w * v.w;
#pragma unroll
    for (int o = 16; o; o >>= 1) s += __shfl_xor_sync(0xffffffffu, s, o);
    if (lane == 0) {
        int lab = is64 ? t32[2 * row] : t32[row];
        g_meta[row] = make_float2(s, (float)lab);
    }
}

// ---------------------------------------------------------------------------
// Tile loader: 128 rows x 512B (hi|lo) -> smem rows stride 528B. 512 threads.
// ---------------------------------------------------------------------------
__device__ __forceinline__ void load_tile(unsigned dst_u32, int rowbase, int tid) {
#pragma unroll
    for (int i = 0; i < 8; i++) {
        int idx = tid + i * NTHREADS;        // 0..4095 16B pieces
        int row = idx >> 5;
        int q   = idx & 31;
        cp16(dst_u32 + (unsigned)(row * ROW_B + q * 16),
             g_split + (size_t)(rowbase + row) * 256 + q * 8);
    }
}
__device__ __forceinline__ void load_meta(unsigned dst_u32, int rowbase, int tid) {
    if (tid < 64) cp16(dst_u32 + tid * 16, g_meta + rowbase + tid * 2);
}

// ---------------------------------------------------------------------------
// Main persistent kernel: triangle tile-pairs on mma.sync bf16-split HMMA.
// 16 warps; warp tile 32x32 (wrow=(wid&3)*32, wcol=(wid>>2)*32).
// ---------------------------------------------------------------------------
__global__ void __launch_bounds__(NTHREADS, 1)
triplet_main_kernel(float* __restrict__ out, int out_size) {
    extern __shared__ char smem[];
    const int tid  = threadIdx.x;
    const int wid  = tid >> 5, lane = tid & 31;
    const int g    = lane >> 2, q = lane & 3;
    const int wrow = (wid & 3) * 32;
    const int wcol = (wid >> 2) * 32;

    const unsigned sb  = smem_u32(smem);
    const unsigned AsU = sb + SM_A, B0U = sb + SM_B0, B1U = sb + SM_B1;
    const float2* metaI = (const float2*)(smem + SM_METAI);
    const float2* metaJ = (const float2*)(smem + SM_METAJ);

    int u0 = (int)((long long)blockIdx.x * NUNITS / gridDim.x);
    int u1 = (int)((long long)(blockIdx.x + 1) * NUNITS / gridDim.x);
    int ti = 0, rem = u0;
    while (rem >= NTILES - ti) { rem -= NTILES - ti; ti++; }
    int tj = ti + rem;

    // Prologue: A tile + B(u0) tile + meta (one group)
    load_tile(AsU, ti * 128, tid);
    load_meta(sb + SM_METAI, ti * 128, tid);
    load_tile(B0U, tj * 128, tid);
    load_meta(sb + SM_METAJ, tj * 128, tid);
    cp_commit();

    bool alias = false;   // current unit reads A from its B buffer (fresh diagonal)

    for (int u = u0; u < u1; ++u) {
        const int b = (u - u0) & 1;
        int nti = ti, ntj = tj + 1;
        if (ntj == NTILES) { nti = ti + 1; ntj = nti; }
        const bool has_next = (u + 1 < u1);

        int nc = 0;
        if (has_next) {
            load_tile(b ? B0U : B1U, ntj * 128, tid);
            load_meta(sb + SM_METAJ + (b ^ 1) * 1024, ntj * 128, tid);
            cp_commit(); nc++;
        }
        if (alias && has_next && nti == ti) {   // refill stale A during diagonal unit
            load_tile(AsU, ti * 128, tid);
            load_meta(sb + SM_METAI, ti * 128, tid);
            cp_commit(); nc++;
        }
        cp_waitn(nc);
        __syncthreads();

        const unsigned bU = b ? B1U : B0U;
        const unsigned aU = alias ? bU : AsU;
        const float2* mI = alias ? (metaJ + b * 128) : metaI;
        const float2* mJ = metaJ + b * 128;

        // Lane base addresses for ldmatrix (x4 quad-matrix layout).
        const unsigned aA = aU + (unsigned)((wrow + (lane & 15)) * ROW_B + (lane >> 4) * 16);
        const unsigned bA = bU + (unsigned)((wcol + ((lane >> 4) * 8) + (lane & 7)) * ROW_B
                                            + ((lane >> 3) & 1) * 16);

        float acc[2][4][4];
#pragma unroll
        for (int mf = 0; mf < 2; mf++)
#pragma unroll
            for (int nf = 0; nf < 4; nf++)
#pragma unroll
                for (int e = 0; e < 4; e++) acc[mf][nf][e] = 0.0f;

#pragma unroll
        for (int ks = 0; ks < 8; ks++) {
            const unsigned ko = ks * 32;          // k16 step, bytes
            uint32_t ah[2][4], al[2][4], bh[2][4], bl[2][4];
#pragma unroll
            for (int mf = 0; mf < 2; mf++) {
                ldmx4(ah[mf], aA + mf * (16 * ROW_B) + ko);         // A hi
                ldmx4(al[mf], aA + mf * (16 * ROW_B) + 256 + ko);   // A lo (elem offset 128)
            }
#pragma unroll
            for (int nb = 0; nb < 2; nb++) {
                ldmx4(bh[nb], bA + nb * (16 * ROW_B) + ko);         // B hi
                ldmx4(bl[nb], bA + nb * (16 * ROW_B) + 256 + ko);   // B lo
            }
#pragma unroll
            for (int mf = 0; mf < 2; mf++)
#pragma unroll
                for (int nb = 0; nb < 2; nb++) {
                    mma16816(acc[mf][nb * 2],     ah[mf], bh[nb][0], bh[nb][1]);  // hh
                    mma16816(acc[mf][nb * 2 + 1], ah[mf], bh[nb][2], bh[nb][3]);
                    mma16816(acc[mf][nb * 2],     ah[mf], bl[nb][0], bl[nb][1]);  // hl
                    mma16816(acc[mf][nb * 2 + 1], ah[mf], bl[nb][2], bl[nb][3]);
                    mma16816(acc[mf][nb * 2],     al[mf], bh[nb][0], bh[nb][1]);  // lh
                    mma16816(acc[mf][nb * 2 + 1], al[mf], bh[nb][2], bh[nb][3]);
                }
        }

        // ---- Epilogue: mine d^2 from fragments (row + col sides) ----
        float si4[4], li4[4];
#pragma unroll
        for (int rr = 0; rr < 4; rr++) {
            float2 m = mI[wrow + (rr >> 1) * 16 + (rr & 1) * 8 + g];
            si4[rr] = m.x; li4[rr] = m.y;
        }
        float sjv[8], ljv[8];
#pragma unroll
        for (int cc = 0; cc < 8; cc++) {
            float2 m = mJ[wcol + (cc >> 1) * 8 + q * 2 + (cc & 1)];
            sjv[cc] = m.x; ljv[cc] = m.y;
        }
        float ap4[4], an4[4], apc[8], anc[8];
#pragma unroll
        for (int rr = 0; rr < 4; rr++) { ap4[rr] = 0.0f; an4[rr] = __int_as_float(0x7f800000); }
#pragma unroll
        for (int cc = 0; cc < 8; cc++) { apc[cc] = 0.0f; anc[cc] = __int_as_float(0x7f800000); }

#pragma unroll
        for (int mf = 0; mf < 2; mf++)
#pragma unroll
            for (int nf = 0; nf < 4; nf++)
#pragma unroll
                for (int e = 0; e < 4; e++) {
                    int rr = mf * 2 + (e >> 1);
                    int cc = nf * 2 + (e & 1);
                    float d2 = fmaf(-2.0f, acc[mf][nf][e], si4[rr] + sjv[cc]);
                    d2 = fmaxf(d2, 1e-12f);
                    if (li4[rr] == ljv[cc]) {
                        ap4[rr] = fmaxf(ap4[rr], d2); apc[cc] = fmaxf(apc[cc], d2);
                    } else {
                        an4[rr] = fminf(an4[rr], d2); anc[cc] = fminf(anc[cc], d2);
                    }
                }

        // Row side: reduce over the quad (lanes share row when g equal).
#pragma unroll
        for (int o = 1; o <= 2; o <<= 1)
#pragma unroll
            for (int rr = 0; rr < 4; rr++) {
                ap4[rr] = fmaxf(ap4[rr], __shfl_xor_sync(0xffffffffu, ap4[rr], o));
                an4[rr] = fminf(an4[rr], __shfl_xor_sync(0xffffffffu, an4[rr], o));
            }
        if (q == 0) {
#pragma unroll
            for (int rr = 0; rr < 4; rr++) {
                int row = ti * 128 + wrow + (rr >> 1) * 16 + (rr & 1) * 8 + g;
                atomicMax(&g_ap2[row], __float_as_uint(ap4[rr]));
                atomicMin(&g_an2[row], __float_as_uint(an4[rr]));
            }
        }
        // Col side: reduce over g (xor 4,8,16), lanes 0-3 write.
#pragma unroll
        for (int o = 4; o <= 16; o <<= 1)
#pragma unroll
            for (int cc = 0; cc < 8; cc++) {
                apc[cc] = fmaxf(apc[cc], __shfl_xor_sync(0xffffffffu, apc[cc], o));
                anc[cc] = fminf(anc[cc], __shfl_xor_sync(0xffffffffu, anc[cc], o));
            }
        if (lane < 4) {
#pragma unroll
            for (int cc = 0; cc < 8; cc++) {
                int col = tj * 128 + wcol + (cc >> 1) * 8 + q * 2 + (cc & 1);
                atomicMax(&g_ap2[col], __float_as_uint(apc[cc]));
                atomicMin(&g_an2[col], __float_as_uint(anc[cc]));
            }
        }
        __syncthreads();   // all reads of current buffers done before next prefetch

        alias = has_next && (nti != ti);
        ti = nti; tj = ntj;
    }

    // ---- Inline finalize: last CTA computes loss + precision ----
    __threadfence();
    __syncthreads();
    __shared__ unsigned s_rank;
    if (tid == 0) s_rank = atomicAdd(&g_done, 1u);
    __syncthreads();
    if (s_rank == (unsigned)(gridDim.x - 1)) {
        float* scrL = (float*)smem;
        float* scrP = scrL + NTHREADS;
        float loss = 0.0f, prec = 0.0f;
        for (int i = tid; i < NROWS; i += NTHREADS) {
            float dap = sqrtf(__uint_as_float(__ldcg(&g_ap2[i])));
            float dan = sqrtf(__uint_as_float(__ldcg(&g_an2[i])));
            loss += fmaxf(0.0f, MARGIN_F - (dan - dap));
            prec += (dan > dap) ? 1.0f : 0.0f;
        }
        scrL[tid] = loss; scrP[tid] = prec;
        __syncthreads();
#pragma unroll
        for (int s = NTHREADS / 2; s > 0; s >>= 1) {
            if (tid < s) { scrL[tid] += scrL[tid + s]; scrP[tid] += scrP[tid + s]; }
            __syncthreads();
        }
        if (tid == 0) {
            out[0] = scrL[0] / (float)NROWS;
            if (out_size > 1) out[1] = scrP[0] / (float)NROWS;
            g_done = 0;
        }
    }
}

// ---------------------------------------------------------------------------
extern "C" void kernel_launch(void* const* d_in, const int* in_sizes, int n_in,
                              void* d_out, int out_size) {
    const float* x   = (const float*)d_in[0];
    const int*   t32 = (const int*)d_in[1];
    (void)in_sizes; (void)n_in;

    cudaFuncSetAttribute(triplet_main_kernel,
                         cudaFuncAttributeMaxDynamicSharedMemorySize, SM_TOTAL);
    prep_kernel<<<NROWS * 32 / 256, 256>>>(x, t32);
    triplet_main_kernel<<<GRID_MAIN, NTHREADS, SM_TOTAL>>>((float*)d_out, out_size);
}

// round 14
// speedup vs baseline: 2.0787x; 1.0284x over previous
#include <cuda_runtime.h>
#include <cuda_bf16.h>
#include <cstdint>

#define NROWS 8192
#define DIM   128
#define NTILES 64
#define NUNITS (NTILES * (NTILES + 1) / 2)   // 2080
#define GRID_MAIN 148
#define NTHREADS 512
#define MARGIN_F 0.3f

#define ROW_B   528                           // smem bytes/row: 33*16 (odd) -> ldmatrix conflict-free
#define TILE_BYTES (128 * ROW_B)              // 67584
#define SM_A     0
#define SM_B0    TILE_BYTES
#define SM_B1    (2 * TILE_BYTES)
#define SM_METAI (3 * TILE_BYTES)             // 128 float2
#define SM_METAJ (SM_METAI + 1024)            // 2 x 128 float2
#define SM_TOTAL (SM_METAJ + 2048)

__device__ unsigned int  g_ap2[NROWS];
__device__ unsigned int  g_an2[NROWS];
__device__ float2        g_meta[NROWS];              // (||x||^2 fp32, label-as-float)
__device__ unsigned int  g_done;
__device__ __align__(512) __nv_bfloat16 g_split[NROWS * 256]; // per row: 128 hi | 128 lo

// ---------------------------------------------------------------------------
__device__ __forceinline__ unsigned smem_u32(const void* p) {
    unsigned r;
    asm("{ .reg .u64 t; cvta.to.shared.u64 t, %1; cvt.u32.u64 %0, t; }" : "=r"(r) : "l"(p));
    return r;
}
__device__ __forceinline__ void cp16(unsigned dst, const void* src) {
    asm volatile("cp.async.cg.shared.global [%0], [%1], 16;" :: "r"(dst), "l"(src));
}
__device__ __forceinline__ void cp_commit() { asm volatile("cp.async.commit_group;"); }
__device__ __forceinline__ void cp_waitn(int n) {
    if (n == 0)      asm volatile("cp.async.wait_group 0;" ::: "memory");
    else if (n == 1) asm volatile("cp.async.wait_group 1;" ::: "memory");
    else             asm volatile("cp.async.wait_group 2;" ::: "memory");
}
__device__ __forceinline__ void ldmx4(uint32_t* r, unsigned addr) {
    asm volatile("ldmatrix.sync.aligned.m8n8.x4.shared.b16 {%0,%1,%2,%3}, [%4];"
                 : "=r"(r[0]), "=r"(r[1]), "=r"(r[2]), "=r"(r[3]) : "r"(addr));
}
__device__ __forceinline__ void mma16816(float* d, const uint32_t* a, uint32_t b0, uint32_t b1) {
    asm volatile("mma.sync.aligned.m16n8k16.row.col.f32.bf16.bf16.f32 "
                 "{%0,%1,%2,%3}, {%4,%5,%6,%7}, {%8,%9}, {%0,%1,%2,%3};"
                 : "+f"(d[0]), "+f"(d[1]), "+f"(d[2]), "+f"(d[3])
                 : "r"(a[0]), "r"(a[1]), "r"(a[2]), "r"(a[3]), "r"(b0), "r"(b1));
}

// ---------------------------------------------------------------------------
// Prep: init mining buffers, bf16 hi/lo split, fp32 norms, labels. 1 warp/row.
// ---------------------------------------------------------------------------
__global__ void prep_kernel(const float* __restrict__ x, const int* __restrict__ t32) {
    int tid = threadIdx.x;
    int gid = blockIdx.x * 256 + tid;
    if (gid < NROWS) { g_ap2[gid] = 0u; g_an2[gid] = 0x7f800000u; }

    __shared__ int s_all64;
    if (tid == 0) s_all64 = 1;
    __syncthreads();
    int local = 1;
    for (int i = tid; i < 4096; i += 256)
        if (t32[2 * i + 1] != 0) local = 0;
    if (!local) atomicAnd(&s_all64, 0);
    __syncthreads();
    const bool is64 = (s_all64 != 0);

    int row = gid >> 5, lane = gid & 31;
    float4 v = reinterpret_cast<const float4*>(x + (size_t)row * DIM)[lane];
    __nv_bfloat16 h0 = __float2bfloat16(v.x), h1 = __float2bfloat16(v.y);
    __nv_bfloat16 h2 = __float2bfloat16(v.z), h3 = __float2bfloat16(v.w);
    __nv_bfloat16 l0 = __float2bfloat16(v.x - __bfloat162float(h0));
    __nv_bfloat16 l1 = __float2bfloat16(v.y - __bfloat162float(h1));
    __nv_bfloat16 l2 = __float2bfloat16(v.z - __bfloat162float(h2));
    __nv_bfloat16 l3 = __float2bfloat16(v.w - __bfloat162float(h3));
    __nv_bfloat162* ph = reinterpret_cast<__nv_bfloat162*>(g_split + (size_t)row * 256 + lane * 4);
    __nv_bfloat162* pl = reinterpret_cast<__nv_bfloat162*>(g_split + (size_t)row * 256 + 128 + lane * 4);
    ph[0] = __halves2bfloat162(h0, h1); ph[1] = __halves2bfloat162(h2, h3);
    pl[0] = __halves2bfloat162(l0, l1); pl[1] = __halves2bfloat162(l2, l3);

    float s = v.x * v.x + v.y * v.y + v.z * v.z + v.w * v.w;
#pragma unroll
    for (int o = 16; o; o >>= 1) s += __shfl_xor_sync(0xffffffffu, s, o);
    if (lane == 0) {
        int lab = is64 ? t32[2 * row] : t32[row];
        g_meta[row] = make_float2(s, (float)lab);
    }
}

// ---------------------------------------------------------------------------
// Tile loader: 128 rows x 512B (hi|lo) -> smem rows stride 528B. 512 threads.
// ---------------------------------------------------------------------------
__device__ __forceinline__ void load_tile(unsigned dst_u32, int rowbase, int tid) {
#pragma unroll
    for (int i = 0; i < 8; i++) {
        int idx = tid + i * NTHREADS;        // 0..4095 16B pieces
        int row = idx >> 5;
        int q   = idx & 31;
        cp16(dst_u32 + (unsigned)(row * ROW_B + q * 16),
             g_split + (size_t)(rowbase + row) * 256 + q * 8);
    }
}
__device__ __forceinline__ void load_meta(unsigned dst_u32, int rowbase, int tid) {
    if (tid < 64) cp16(dst_u32 + tid * 16, g_meta + rowbase + tid * 2);
}

// ---------------------------------------------------------------------------
// Main persistent kernel: triangle tile-pairs on mma.sync bf16-split HMMA.
// 16 warps; warp tile 32x32 (wrow=(wid&3)*32, wcol=(wid>>2)*32).
// MMA passes (hh, hl, lh) are OUTERMOST so each accumulator quad is touched
// once per 8 HMMAs -> no RAW chain on the tensor pipe.
// ---------------------------------------------------------------------------
__global__ void __launch_bounds__(NTHREADS, 1)
triplet_main_kernel(float* __restrict__ out, int out_size) {
    extern __shared__ char smem[];
    const int tid  = threadIdx.x;
    const int wid  = tid >> 5, lane = tid & 31;
    const int g    = lane >> 2, q = lane & 3;
    const int wrow = (wid & 3) * 32;
    const int wcol = (wid >> 2) * 32;

    const unsigned sb  = smem_u32(smem);
    const unsigned AsU = sb + SM_A, B0U = sb + SM_B0, B1U = sb + SM_B1;
    const float2* metaI = (const float2*)(smem + SM_METAI);
    const float2* metaJ = (const float2*)(smem + SM_METAJ);

    int u0 = (int)((long long)blockIdx.x * NUNITS / gridDim.x);
    int u1 = (int)((long long)(blockIdx.x + 1) * NUNITS / gridDim.x);
    int ti = 0, rem = u0;
    while (rem >= NTILES - ti) { rem -= NTILES - ti; ti++; }
    int tj = ti + rem;

    // Prologue: A tile + B(u0) tile + meta (one group)
    load_tile(AsU, ti * 128, tid);
    load_meta(sb + SM_METAI, ti * 128, tid);
    load_tile(B0U, tj * 128, tid);
    load_meta(sb + SM_METAJ, tj * 128, tid);
    cp_commit();

    bool alias = false;   // current unit reads A from its B buffer (fresh diagonal)

    for (int u = u0; u < u1; ++u) {
        const int b = (u - u0) & 1;
        int nti = ti, ntj = tj + 1;
        if (ntj == NTILES) { nti = ti + 1; ntj = nti; }
        const bool has_next = (u + 1 < u1);

        int nc = 0;
        if (has_next) {
            load_tile(b ? B0U : B1U, ntj * 128, tid);
            load_meta(sb + SM_METAJ + (b ^ 1) * 1024, ntj * 128, tid);
            cp_commit(); nc++;
        }
        if (alias && has_next && nti == ti) {   // refill stale A during diagonal unit
            load_tile(AsU, ti * 128, tid);
            load_meta(sb + SM_METAI, ti * 128, tid);
            cp_commit(); nc++;
        }
        cp_waitn(nc);
        __syncthreads();

        const unsigned bU = b ? B1U : B0U;
        const unsigned aU = alias ? bU : AsU;
        const float2* mI = alias ? (metaJ + b * 128) : metaI;
        const float2* mJ = metaJ + b * 128;

        // Lane base addresses for ldmatrix (x4 quad-matrix layout).
        const unsigned aA = aU + (unsigned)((wrow + (lane & 15)) * ROW_B + (lane >> 4) * 16);
        const unsigned bA = bU + (unsigned)((wcol + ((lane >> 4) * 8) + (lane & 7)) * ROW_B
                                            + ((lane >> 3) & 1) * 16);

        float acc[2][4][4];
#pragma unroll
        for (int mf = 0; mf < 2; mf++)
#pragma unroll
            for (int nf = 0; nf < 4; nf++)
#pragma unroll
                for (int e = 0; e < 4; e++) acc[mf][nf][e] = 0.0f;

#pragma unroll
        for (int ks = 0; ks < 8; ks++) {
            const unsigned ko = ks * 32;          // k16 step, bytes
            uint32_t ah[2][4], al[2][4], bh[2][4], bl[2][4];
#pragma unroll
            for (int mf = 0; mf < 2; mf++) {
                ldmx4(ah[mf], aA + mf * (16 * ROW_B) + ko);         // A hi
                ldmx4(al[mf], aA + mf * (16 * ROW_B) + 256 + ko);   // A lo (elem offset 128)
            }
#pragma unroll
            for (int nb = 0; nb < 2; nb++) {
                ldmx4(bh[nb], bA + nb * (16 * ROW_B) + ko);         // B hi
                ldmx4(bl[nb], bA + nb * (16 * ROW_B) + 256 + ko);   // B lo
            }
            // Pass 1 (hh): 8 HMMAs, each acc quad exactly once.
#pragma unroll
            for (int mf = 0; mf < 2; mf++)
#pragma unroll
                for (int nb = 0; nb < 2; nb++) {
                    mma16816(acc[mf][nb * 2],     ah[mf], bh[nb][0], bh[nb][1]);
                    mma16816(acc[mf][nb * 2 + 1], ah[mf], bh[nb][2], bh[nb][3]);
                }
            // Pass 2 (hl)
#pragma unroll
            for (int mf = 0; mf < 2; mf++)
#pragma unroll
                for (int nb = 0; nb < 2; nb++) {
                    mma16816(acc[mf][nb * 2],     ah[mf], bl[nb][0], bl[nb][1]);
                    mma16816(acc[mf][nb * 2 + 1], ah[mf], bl[nb][2], bl[nb][3]);
                }
            // Pass 3 (lh)
#pragma unroll
            for (int mf = 0; mf < 2; mf++)
#pragma unroll
                for (int nb = 0; nb < 2; nb++) {
                    mma16816(acc[mf][nb * 2],     al[mf], bh[nb][0], bh[nb][1]);
                    mma16816(acc[mf][nb * 2 + 1], al[mf], bh[nb][2], bh[nb][3]);
                }
        }

        // ---- Epilogue: mine d^2 from fragments (row + col sides) ----
        float si4[4], li4[4];
#pragma unroll
        for (int rr = 0; rr < 4; rr++) {
            float2 m = mI[wrow + (rr >> 1) * 16 + (rr & 1) * 8 + g];
            si4[rr] = m.x; li4[rr] = m.y;
        }
        float sjv[8], ljv[8];
#pragma unroll
        for (int cc = 0; cc < 8; cc++) {
            float2 m = mJ[wcol + (cc >> 1) * 8 + q * 2 + (cc & 1)];
            sjv[cc] = m.x; ljv[cc] = m.y;
        }
        float ap4[4], an4[4], apc[8], anc[8];
#pragma unroll
        for (int rr = 0; rr < 4; rr++) { ap4[rr] = 0.0f; an4[rr] = __int_as_float(0x7f800000); }
#pragma unroll
        for (int cc = 0; cc < 8; cc++) { apc[cc] = 0.0f; anc[cc] = __int_as_float(0x7f800000); }

#pragma unroll
        for (int mf = 0; mf < 2; mf++)
#pragma unroll
            for (int nf = 0; nf < 4; nf++)
#pragma unroll
                for (int e = 0; e < 4; e++) {
                    int rr = mf * 2 + (e >> 1);
                    int cc = nf * 2 + (e & 1);
                    float d2 = fmaf(-2.0f, acc[mf][nf][e], si4[rr] + sjv[cc]);
                    d2 = fmaxf(d2, 1e-12f);
                    if (li4[rr] == ljv[cc]) {
                        ap4[rr] = fmaxf(ap4[rr], d2); apc[cc] = fmaxf(apc[cc], d2);
                    } else {
                        an4[rr] = fminf(an4[rr], d2); anc[cc] = fminf(anc[cc], d2);
                    }
                }

        // Row side: reduce over the quad (lanes share row when g equal).
#pragma unroll
        for (int o = 1; o <= 2; o <<= 1)
#pragma unroll
            for (int rr = 0; rr < 4; rr++) {
                ap4[rr] = fmaxf(ap4[rr], __shfl_xor_sync(0xffffffffu, ap4[rr], o));
                an4[rr] = fminf(an4[rr], __shfl_xor_sync(0xffffffffu, an4[rr], o));
            }
        if (q == 0) {
#pragma unroll
            for (int rr = 0; rr < 4; rr++) {
                int row = ti * 128 + wrow + (rr >> 1) * 16 + (rr & 1) * 8 + g;
                atomicMax(&g_ap2[row], __float_as_uint(ap4[rr]));
                atomicMin(&g_an2[row], __float_as_uint(an4[rr]));
            }
        }
        // Col side: reduce over g (xor 4,8,16), lanes 0-3 write.
#pragma unroll
        for (int o = 4; o <= 16; o <<= 1)
#pragma unroll
            for (int cc = 0; cc < 8; cc++) {
                apc[cc] = fmaxf(apc[cc], __shfl_xor_sync(0xffffffffu, apc[cc], o));
                anc[cc] = fminf(anc[cc], __shfl_xor_sync(0xffffffffu, anc[cc], o));
            }
        if (lane < 4) {
#pragma unroll
            for (int cc = 0; cc < 8; cc++) {
                int col = tj * 128 + wcol + (cc >> 1) * 8 + q * 2 + (cc & 1);
                atomicMax(&g_ap2[col], __float_as_uint(apc[cc]));
                atomicMin(&g_an2[col], __float_as_uint(anc[cc]));
            }
        }
        __syncthreads();   // all reads of current buffers done before next prefetch

        alias = has_next && (nti != ti);
        ti = nti; tj = ntj;
    }

    // ---- Inline finalize: last CTA computes loss + precision ----
    __threadfence();
    __syncthreads();
    __shared__ unsigned s_rank;
    if (tid == 0) s_rank = atomicAdd(&g_done, 1u);
    __syncthreads();
    if (s_rank == (unsigned)(gridDim.x - 1)) {
        float* scrL = (float*)smem;
        float* scrP = scrL + NTHREADS;
        float loss = 0.0f, prec = 0.0f;
        for (int i = tid; i < NROWS; i += NTHREADS) {
            float dap = sqrtf(__uint_as_float(__ldcg(&g_ap2[i])));
            float dan = sqrtf(__uint_as_float(__ldcg(&g_an2[i])));
            loss += fmaxf(0.0f, MARGIN_F - (dan - dap));
            prec += (dan > dap) ? 1.0f : 0.0f;
        }
        scrL[tid] = loss; scrP[tid] = prec;
        __syncthreads();
#pragma unroll
        for (int s = NTHREADS / 2; s > 0; s >>= 1) {
            if (tid < s) { scrL[tid] += scrL[tid + s]; scrP[tid] += scrP[tid + s]; }
            __syncthreads();
        }
        if (tid == 0) {
            out[0] = scrL[0] / (float)NROWS;
            if (out_size > 1) out[1] = scrP[0] / (float)NROWS;
            g_done = 0;
        }
    }
}

// ---------------------------------------------------------------------------
extern "C" void kernel_launch(void* const* d_in, const int* in_sizes, int n_in,
                              void* d_out, int out_size) {
    const float* x   = (const float*)d_in[0];
    const int*   t32 = (const int*)d_in[1];
    (void)in_sizes; (void)n_in;

    cudaFuncSetAttribute(triplet_main_kernel,
                         cudaFuncAttributeMaxDynamicSharedMemorySize, SM_TOTAL);
    prep_kernel<<<NROWS * 32 / 256, 256>>>(x, t32);
    triplet_main_kernel<<<GRID_MAIN, NTHREADS, SM_TOTAL>>>((float*)d_out, out_size);
}

// round 17
// speedup vs baseline: 2.1177x; 1.0187x over previous
#include <cuda_runtime.h>
#include <cuda_bf16.h>
#include <cstdint>

#define NROWS 8192
#define DIM   128
#define NTILES 64
#define NUNITS (NTILES * (NTILES + 1) / 2)   // 2080
#define GRID_MAIN 148
#define NTHREADS 512
#define MARGIN_F 0.3f

#define ROW_B   528                           // smem bytes/row: 33*16 (odd) -> ldmatrix conflict-free
#define TILE_BYTES (128 * ROW_B)              // 67584
#define SM_A     0
#define SM_B0    TILE_BYTES
#define SM_B1    (2 * TILE_BYTES)
#define SM_METAI (3 * TILE_BYTES)             // 2 slots x 128 float2 (row parity)
#define SM_METAJ (SM_METAI + 2048)            // 3 slots x 128 float2 (u mod 3)
#define SM_TOTAL (SM_METAJ + 3072)

__device__ unsigned int  g_ap2[NROWS];
__device__ unsigned int  g_an2[NROWS];
__device__ float2        g_meta[NROWS];              // (||x||^2 fp32, label-as-float)
__device__ unsigned int  g_done;
__device__ __align__(512) __nv_bfloat16 g_split[NROWS * 256]; // per row: 128 hi | 128 lo

// ---------------------------------------------------------------------------
__device__ __forceinline__ unsigned smem_u32(const void* p) {
    unsigned r;
    asm("{ .reg .u64 t; cvta.to.shared.u64 t, %1; cvt.u32.u64 %0, t; }" : "=r"(r) : "l"(p));
    return r;
}
__device__ __forceinline__ void cp16(unsigned dst, const void* src) {
    asm volatile("cp.async.cg.shared.global [%0], [%1], 16;" :: "r"(dst), "l"(src));
}
__device__ __forceinline__ void cp_commit() { asm volatile("cp.async.commit_group;"); }
__device__ __forceinline__ void cp_wait0()  { asm volatile("cp.async.wait_group 0;" ::: "memory"); }
__device__ __forceinline__ void ldmx4(uint32_t* r, unsigned addr) {
    asm volatile("ldmatrix.sync.aligned.m8n8.x4.shared.b16 {%0,%1,%2,%3}, [%4];"
                 : "=r"(r[0]), "=r"(r[1]), "=r"(r[2]), "=r"(r[3]) : "r"(addr));
}
__device__ __forceinline__ void mma16816(float* d, const uint32_t* a, uint32_t b0, uint32_t b1) {
    asm volatile("mma.sync.aligned.m16n8k16.row.col.f32.bf16.bf16.f32 "
                 "{%0,%1,%2,%3}, {%4,%5,%6,%7}, {%8,%9}, {%0,%1,%2,%3};"
                 : "+f"(d[0]), "+f"(d[1]), "+f"(d[2]), "+f"(d[3])
                 : "r"(a[0]), "r"(a[1]), "r"(a[2]), "r"(a[3]), "r"(b0), "r"(b1));
}

// ---------------------------------------------------------------------------
// Prep: init mining buffers, bf16 hi/lo split, fp32 norms, labels. 1 warp/row.
// ---------------------------------------------------------------------------
__global__ void prep_kernel(const float* __restrict__ x, const int* __restrict__ t32) {
    int tid = threadIdx.x;
    int gid = blockIdx.x * 256 + tid;
    if (gid < NROWS) { g_ap2[gid] = 0u; g_an2[gid] = 0x7f800000u; }

    __shared__ int s_all64;
    if (tid == 0) s_all64 = 1;
    __syncthreads();
    int local = 1;
    for (int i = tid; i < 4096; i += 256)
        if (t32[2 * i + 1] != 0) local = 0;
    if (!local) atomicAnd(&s_all64, 0);
    __syncthreads();
    const bool is64 = (s_all64 != 0);

    int row = gid >> 5, lane = gid & 31;
    float4 v = reinterpret_cast<const float4*>(x + (size_t)row * DIM)[lane];
    __nv_bfloat16 h0 = __float2bfloat16(v.x), h1 = __float2bfloat16(v.y);
    __nv_bfloat16 h2 = __float2bfloat16(v.z), h3 = __float2bfloat16(v.w);
    __nv_bfloat16 l0 = __float2bfloat16(v.x - __bfloat162float(h0));
    __nv_bfloat16 l1 = __float2bfloat16(v.y - __bfloat162float(h1));
    __nv_bfloat16 l2 = __float2bfloat16(v.z - __bfloat162float(h2));
    __nv_bfloat16 l3 = __float2bfloat16(v.w - __bfloat162float(h3));
    __nv_bfloat162* ph = reinterpret_cast<__nv_bfloat162*>(g_split + (size_t)row * 256 + lane * 4);
    __nv_bfloat162* pl = reinterpret_cast<__nv_bfloat162*>(g_split + (size_t)row * 256 + 128 + lane * 4);
    ph[0] = __halves2bfloat162(h0, h1); ph[1] = __halves2bfloat162(h2, h3);
    pl[0] = __halves2bfloat162(l0, l1); pl[1] = __halves2bfloat162(l2, l3);

    float s = v.x * v.x + v.y * v.y + v.z * v.z + v.w * v.w;
#pragma unroll
    for (int o = 16; o; o >>= 1) s += __shfl_xor_sync(0xffffffffu, s, o);
    if (lane == 0) {
        int lab = is64 ? t32[2 * row] : t32[row];
        g_meta[row] = make_float2(s, (float)lab);
    }
}

// ---------------------------------------------------------------------------
// Tile loader: 128 rows x 512B (hi|lo) -> smem rows stride 528B. 512 threads.
// ---------------------------------------------------------------------------
__device__ __forceinline__ void load_tile(unsigned dst_u32, int rowbase, int tid) {
#pragma unroll
    for (int i = 0; i < 8; i++) {
        int idx = tid + i * NTHREADS;        // 0..4095 16B pieces
        int row = idx >> 5;
        int q   = idx & 31;
        cp16(dst_u32 + (unsigned)(row * ROW_B + q * 16),
             g_split + (size_t)(rowbase + row) * 256 + q * 8);
    }
}
__device__ __forceinline__ void load_meta(unsigned dst_u32, int rowbase, int tid) {
    if (tid < 64) cp16(dst_u32 + tid * 16, g_meta + rowbase + tid * 2);
}

// ---------------------------------------------------------------------------
// Epilogue: mine d^2 from fragments of the PREVIOUS unit (row + col sides).
// skip_col for diagonal units (computed matrix is exactly symmetric).
// ---------------------------------------------------------------------------
__device__ __forceinline__ void epilogue_mine(
    const float (&acc)[2][4][4], int pti, int ptj,
    const float2* mI, const float2* mJ, bool skip_col,
    int lane, int g, int q, int wrow, int wcol)
{
    float si4[4], li4[4];
#pragma unroll
    for (int rr = 0; rr < 4; rr++) {
        float2 m = mI[wrow + (rr >> 1) * 16 + (rr & 1) * 8 + g];
        si4[rr] = m.x; li4[rr] = m.y;
    }
    float sjv[8], ljv[8];
#pragma unroll
    for (int cc = 0; cc < 8; cc++) {
        float2 m = mJ[wcol + (cc >> 1) * 8 + q * 2 + (cc & 1)];
        sjv[cc] = m.x; ljv[cc] = m.y;
    }
    float ap4[4], an4[4], apc[8], anc[8];
#pragma unroll
    for (int rr = 0; rr < 4; rr++) { ap4[rr] = 0.0f; an4[rr] = __int_as_float(0x7f800000); }
#pragma unroll
    for (int cc = 0; cc < 8; cc++) { apc[cc] = 0.0f; anc[cc] = __int_as_float(0x7f800000); }

#pragma unroll
    for (int mf = 0; mf < 2; mf++)
#pragma unroll
        for (int nf = 0; nf < 4; nf++)
#pragma unroll
            for (int e = 0; e < 4; e++) {
                int rr = mf * 2 + (e >> 1);
                int cc = nf * 2 + (e & 1);
                float d2 = fmaf(-2.0f, acc[mf][nf][e], si4[rr] + sjv[cc]);
                d2 = fmaxf(d2, 1e-12f);
                if (li4[rr] == ljv[cc]) {
                    ap4[rr] = fmaxf(ap4[rr], d2); apc[cc] = fmaxf(apc[cc], d2);
                } else {
                    an4[rr] = fminf(an4[rr], d2); anc[cc] = fminf(anc[cc], d2);
                }
            }

    // Row side: reduce over the quad, lane q==0 writes atomics.
#pragma unroll
    for (int o = 1; o <= 2; o <<= 1)
#pragma unroll
        for (int rr = 0; rr < 4; rr++) {
            ap4[rr] = fmaxf(ap4[rr], __shfl_xor_sync(0xffffffffu, ap4[rr], o));
            an4[rr] = fminf(an4[rr], __shfl_xor_sync(0xffffffffu, an4[rr], o));
        }
    if (q == 0) {
#pragma unroll
        for (int rr = 0; rr < 4; rr++) {
            int row = pti * 128 + wrow + (rr >> 1) * 16 + (rr & 1) * 8 + g;
            atomicMax(&g_ap2[row], __float_as_uint(ap4[rr]));
            atomicMin(&g_an2[row], __float_as_uint(an4[rr]));
        }
    }
    if (skip_col) return;   // diagonal unit: col mining is exactly redundant
    // Col side: reduce over g (xor 4,8,16), lanes 0-3 write.
#pragma unroll
    for (int o = 4; o <= 16; o <<= 1)
#pragma unroll
        for (int cc = 0; cc < 8; cc++) {
            apc[cc] = fmaxf(apc[cc], __shfl_xor_sync(0xffffffffu, apc[cc], o));
            anc[cc] = fminf(anc[cc], __shfl_xor_sync(0xffffffffu, anc[cc], o));
        }
    if (lane < 4) {
#pragma unroll
        for (int cc = 0; cc < 8; cc++) {
            int col = ptj * 128 + wcol + (cc >> 1) * 8 + q * 2 + (cc & 1);
            atomicMax(&g_ap2[col], __float_as_uint(apc[cc]));
            atomicMin(&g_an2[col], __float_as_uint(anc[cc]));
        }
    }
}

// ---------------------------------------------------------------------------
// Main persistent kernel. Pipelined: per unit u the schedule is
//   wait0 -> sync -> issue cp(u+1) -> epilogue(u-1) -> kloop(u)
// ONE barrier per unit; epilogue stalls hide under other warps' HMMA issue.
// ---------------------------------------------------------------------------
__global__ void __launch_bounds__(NTHREADS, 1)
triplet_main_kernel(float* __restrict__ out, int out_size) {
    extern __shared__ char smem[];
    const int tid  = threadIdx.x;
    const int wid  = tid >> 5, lane = tid & 31;
    const int g    = lane >> 2, q = lane & 3;
    const int wrow = (wid & 3) * 32;
    const int wcol = (wid >> 2) * 32;

    const unsigned sb  = smem_u32(smem);
    const unsigned AsU = sb + SM_A, B0U = sb + SM_B0, B1U = sb + SM_B1;
    const float2* metaI = (const float2*)(smem + SM_METAI);   // 2 slots x 128
    const float2* metaJ = (const float2*)(smem + SM_METAJ);   // 3 slots x 128

    int u0 = (int)((long long)blockIdx.x * NUNITS / gridDim.x);
    int u1 = (int)((long long)(blockIdx.x + 1) * NUNITS / gridDim.x);
    int ti = 0, rem = u0;
    while (rem >= NTILES - ti) { rem -= NTILES - ti; ti++; }
    int tj = ti + rem;

    // Prologue: A tile (metaI slot ti&1) + B(u0) tile (metaJ slot 0)
    load_tile(AsU, ti * 128, tid);
    load_meta(sb + SM_METAI + (ti & 1) * 1024, ti * 128, tid);
    load_tile(B0U, tj * 128, tid);
    load_meta(sb + SM_METAJ, tj * 128, tid);
    cp_commit();

    bool alias_cur = false;            // current unit reads A from its B buffer
    bool have_prev = false;
    int  pti = 0, ptj = 0;
    const float2 *pmI = metaI, *pmJ = metaJ;
    float acc[2][4][4];

    for (int u = u0; u < u1; ++u) {
        const int b = (u - u0) & 1;
        const int s = (u - u0) % 3;
        int nti = ti, ntj = tj + 1;
        if (ntj == NTILES) { nti = ti + 1; ntj = nti; }
        const bool has_next = (u + 1 < u1);

        cp_wait0();
        __syncthreads();   // u's buffers ready; all warps past kloop(u-1)

        // Issue loads for u+1 (into the buffer last read at u-1: safe post-sync).
        if (has_next) {
            load_tile(b ? B0U : B1U, ntj * 128, tid);
            load_meta(sb + SM_METAJ + ((u + 1 - u0) % 3) * 1024, ntj * 128, tid);
        }
        // Stale-diagonal: refill A for the rest of this row while kloop reads B.
        if (alias_cur && has_next && nti == ti) {
            load_tile(AsU, ti * 128, tid);
            load_meta(sb + SM_METAI + (ti & 1) * 1024, ti * 128, tid);
        }
        cp_commit();

        // Epilogue of previous unit — overlaps other warps' kloop(u) HMMAs.
        if (have_prev)
            epilogue_mine(acc, pti, ptj, pmI, pmJ, pti == ptj,
                          lane, g, q, wrow, wcol);

        // ---- kloop(u) ----
        const unsigned bU = b ? B1U : B0U;
        const unsigned aU = alias_cur ? bU : AsU;
        const unsigned aA = aU + (unsigned)((wrow + (lane & 15)) * ROW_B + (lane >> 4) * 16);
        const unsigned bA = bU + (unsigned)((wcol + ((lane >> 4) * 8) + (lane & 7)) * ROW_B
                                            + ((lane >> 3) & 1) * 16);
#pragma unroll
        for (int mf = 0; mf < 2; mf++)
#pragma unroll
            for (int nf = 0; nf < 4; nf++)
#pragma unroll
                for (int e = 0; e < 4; e++) acc[mf][nf][e] = 0.0f;

#pragma unroll
        for (int ks = 0; ks < 8; ks++) {
            const unsigned ko = ks * 32;
            uint32_t ah[2][4], al[2][4], bh[2][4], bl[2][4];
#pragma unroll
            for (int mf = 0; mf < 2; mf++) {
                ldmx4(ah[mf], aA + mf * (16 * ROW_B) + ko);
                ldmx4(al[mf], aA + mf * (16 * ROW_B) + 256 + ko);
            }
#pragma unroll
            for (int nb = 0; nb < 2; nb++) {
                ldmx4(bh[nb], bA + nb * (16 * ROW_B) + ko);
                ldmx4(bl[nb], bA + nb * (16 * ROW_B) + 256 + ko);
            }
#pragma unroll
            for (int mf = 0; mf < 2; mf++)
#pragma unroll
                for (int nb = 0; nb < 2; nb++) {
                    mma16816(acc[mf][nb * 2],     ah[mf], bh[nb][0], bh[nb][1]);
                    mma16816(acc[mf][nb * 2 + 1], ah[mf], bh[nb][2], bh[nb][3]);
                }
#pragma unroll
            for (int mf = 0; mf < 2; mf++)
#pragma unroll
                for (int nb = 0; nb < 2; nb++) {
                    mma16816(acc[mf][nb * 2],     ah[mf], bl[nb][0], bl[nb][1]);
                    mma16816(acc[mf][nb * 2 + 1], ah[mf], bl[nb][2], bl[nb][3]);
                }
#pragma unroll
            for (int mf = 0; mf < 2; mf++)
#pragma unroll
                for (int nb = 0; nb < 2; nb++) {
                    mma16816(acc[mf][nb * 2],     al[mf], bh[nb][0], bh[nb][1]);
                    mma16816(acc[mf][nb * 2 + 1], al[mf], bh[nb][2], bh[nb][3]);
                }
        }

        // Save prev-unit context for the deferred epilogue.
        pti = ti; ptj = tj;
        pmI = alias_cur ? (metaJ + s * 128) : (metaI + (ti & 1) * 128);
        pmJ = metaJ + s * 128;
        have_prev = true;

        alias_cur = has_next && (nti != ti);  // next unit is a fresh-row diagonal
        ti = nti; tj = ntj;
    }

    // Tail epilogue (last unit).
    if (have_prev)
        epilogue_mine(acc, pti, ptj, pmI, pmJ, pti == ptj,
                      lane, g, q, wrow, wcol);

    // ---- Inline finalize: last CTA computes loss + precision ----
    __threadfence();
    __syncthreads();
    __shared__ unsigned s_rank;
    if (tid == 0) s_rank = atomicAdd(&g_done, 1u);
    __syncthreads();
    if (s_rank == (unsigned)(gridDim.x - 1)) {
        float* scrL = (float*)smem;
        float* scrP = scrL + NTHREADS;
        float loss = 0.0f, prec = 0.0f;
        for (int i = tid; i < NROWS; i += NTHREADS) {
            float dap = sqrtf(__uint_as_float(__ldcg(&g_ap2[i])));
            float dan = sqrtf(__uint_as_float(__ldcg(&g_an2[i])));
            loss += fmaxf(0.0f, MARGIN_F - (dan - dap));
            prec += (dan > dap) ? 1.0f : 0.0f;
        }
        scrL[tid] = loss; scrP[tid] = prec;
        __syncthreads();
#pragma unroll
        for (int s = NTHREADS / 2; s > 0; s >>= 1) {
            if (tid < s) { scrL[tid] += scrL[tid + s]; scrP[tid] += scrP[tid + s]; }
            __syncthreads();
        }
        if (tid == 0) {
            out[0] = scrL[0] / (float)NROWS;
            if (out_size > 1) out[1] = scrP[0] / (float)NROWS;
            g_done = 0;
        }
    }
}

// ---------------------------------------------------------------------------
extern "C" void kernel_launch(void* const* d_in, const int* in_sizes, int n_in,
                              void* d_out, int out_size) {
    const float* x   = (const float*)d_in[0];
    const int*   t32 = (const int*)d_in[1];
    (void)in_sizes; (void)n_in;

    cudaFuncSetAttribute(triplet_main_kernel,
                         cudaFuncAttributeMaxDynamicSharedMemorySize, SM_TOTAL);
    prep_kernel<<<NROWS * 32 / 256, 256>>>(x, t32);
    triplet_main_kernel<<<GRID_MAIN, NTHREADS, SM_TOTAL>>>((float*)d_out, out_size);
}